// round 14
// baseline (speedup 1.0000x reference)
#include <cuda_runtime.h>
#include <cuda_bf16.h>
#include <math.h>
#include <stdint.h>

#define NB    32
#define HID   1024
#define TSTEP 63
#define ENCL  64
#define G3    3072
#define PADK  36
#define NBLK  256
#define NLEAF 16

#define DEC_HIDS_ELEMS (NB * TSTEP * HID)
#define ATTS_ELEMS     (NB * ENCL * TSTEP)
#define ATT_BASE       DEC_HIDS_ELEMS
#define DECPREV_BASE   (DEC_HIDS_ELEMS + ATTS_ELEMS)

// ---------------------------------------------------------------------------
// Scratch
// ---------------------------------------------------------------------------
__device__ float g_enc_proj[NB * ENCL * 1024];      // enc @ W_att_enc^T (fp32)
__device__ float g_encW    [NB * ENCL * 1024];      // enc @ W_ctx^T (tf32)
__device__ float g_emb_src [TSTEP * NB * 1024];     // gathered embeddings
__device__ float g_emb_merged[TSTEP * NB * 1024];   // emb@W_in^T + biases (tf32)
__device__ float g_bias[1024];                      // b_in + b_ctx
__device__ float g_encWih0T[NB * G3 * ENCL];        // [n][jfull][l] (tf32)
__device__ float g_precomp0[TSTEP * NB * G3];       // emb_merged @ W_ih0^T (tf32)

__device__ float g_h[2 * NB * HID];
__device__ float g_score[NB * ENCL];

__device__ float g_dp_part [8 * NB * HID];
__device__ float g_gh0_part[8 * NB * G3];
__device__ float g_gh1_part[8 * NB * G3];
__device__ float g_gi_part [8 * NB * G3];

// Hierarchical barrier state (monotonic counters; no resets per phase)
__device__ unsigned g_leaf[NLEAF * 32];   // one 128B line per leaf
__device__ unsigned g_master;
__device__ unsigned g_gen2;

// ---------------------------------------------------------------------------
// Helpers
// ---------------------------------------------------------------------------
__device__ __forceinline__ float tanh_fast(float x) {
    float y;
    asm("tanh.approx.f32 %0, %1;" : "=f"(y) : "f"(x));
    return y;
}
__device__ __forceinline__ uint32_t f2tf(float x) {
    uint32_t r;
    asm("cvt.rna.tf32.f32 %0, %1;" : "=r"(r) : "f"(x));
    return r;
}
__device__ __forceinline__ void mma8(float* d, const uint32_t* a,
                                     uint32_t b0, uint32_t b1) {
    asm volatile(
        "mma.sync.aligned.m16n8k8.row.col.f32.tf32.tf32.f32 "
        "{%0,%1,%2,%3}, {%4,%5,%6,%7}, {%8,%9}, {%0,%1,%2,%3};"
        : "+f"(d[0]), "+f"(d[1]), "+f"(d[2]), "+f"(d[3])
        : "r"(a[0]), "r"(a[1]), "r"(a[2]), "r"(a[3]), "r"(b0), "r"(b1));
}
__device__ __forceinline__ void cp16(void* smem_dst, const void* gsrc) {
    unsigned s = (unsigned)__cvta_generic_to_shared(smem_dst);
    asm volatile("cp.async.ca.shared.global [%0], [%1], 16;" :: "r"(s), "l"(gsrc));
}
__device__ __forceinline__ void cp_commit() {
    asm volatile("cp.async.commit_group;");
}
template<int N> __device__ __forceinline__ void cp_wait() {
    asm volatile("cp.async.wait_group %0;" :: "n"(N));
}

// Hierarchical grid barrier: 16 leaf counters (16 blocks each) + master.
// Counters are monotonic: after phase ph, each leaf has ph*16, master ph*16.
__device__ __forceinline__ void gridbar(unsigned ph) {
    __syncthreads();
    if (threadIdx.x == 0) {
        unsigned* leaf = &g_leaf[(blockIdx.x & (NLEAF - 1)) * 32];
        unsigned v;
        asm volatile("atom.add.acq_rel.gpu.u32 %0, [%1], 1;"
                     : "=r"(v) : "l"(leaf) : "memory");
        bool released = false;
        if (v + 1 == ph * (NBLK / NLEAF)) {          // last arrival in leaf
            unsigned m;
            asm volatile("atom.add.acq_rel.gpu.u32 %0, [%1], 1;"
                         : "=r"(m) : "l"(&g_master) : "memory");
            if (m + 1 == ph * NLEAF) {               // last leaf
                asm volatile("st.release.gpu.u32 [%0], %1;"
                             :: "l"(&g_gen2), "r"(ph) : "memory");
                released = true;
            }
        }
        if (!released) {
            unsigned g;
            do {
                asm volatile("ld.acquire.gpu.u32 %0, [%1];"
                             : "=r"(g) : "l"(&g_gen2) : "memory");
            } while (g < ph);
        }
    }
    __syncthreads();
}

// ---------------------------------------------------------------------------
// tf32 tc GEMM: out[32 x 128cols @j0] = A[32 x (NCH*32)k @k0] @ W^T
// ---------------------------------------------------------------------------
__device__ __forceinline__ void stage_chunk(float* Asb, float* Wsb,
                                            const float* __restrict__ A,
                                            const float* __restrict__ W,
                                            int j0, int kg, int tid) {
#pragma unroll
    for (int i = 0; i < 2; i++) {
        int idx = tid + i * 128;
        int row = idx >> 3, seg = idx & 7;
        cp16(Asb + row * PADK + seg * 4, A + (size_t)row * 1024 + kg + seg * 4);
    }
#pragma unroll
    for (int i = 0; i < 8; i++) {
        int idx = tid + i * 128;
        int row = idx >> 3, seg = idx & 7;
        cp16(Wsb + row * PADK + seg * 4, W + (size_t)(j0 + row) * 1024 + kg + seg * 4);
    }
    cp_commit();
}

#define MMA_CHUNK_BODY(as, ws)                                                 \
    {                                                                          \
        _Pragma("unroll")                                                      \
        for (int ks = 0; ks < 4; ks++) {                                       \
            int kq = ks * 8 + q;                                               \
            uint32_t afr[2][4];                                                \
            _Pragma("unroll")                                                  \
            for (int mt = 0; mt < 2; mt++) {                                   \
                afr[mt][0] = f2tf((as)[(mt * 16 + r)     * PADK + kq]);        \
                afr[mt][1] = f2tf((as)[(mt * 16 + r + 8) * PADK + kq]);        \
                afr[mt][2] = f2tf((as)[(mt * 16 + r)     * PADK + kq + 4]);    \
                afr[mt][3] = f2tf((as)[(mt * 16 + r + 8) * PADK + kq + 4]);    \
            }                                                                  \
            _Pragma("unroll")                                                  \
            for (int nt = 0; nt < 4; nt++) {                                   \
                int n = wid * 32 + nt * 8 + r;                                 \
                uint32_t b0 = f2tf((ws)[n * PADK + ks * 8 + q]);               \
                uint32_t b1 = f2tf((ws)[n * PADK + ks * 8 + 4 + q]);           \
                mma8(acc[0][nt], afr[0], b0, b1);                              \
                mma8(acc[1][nt], afr[1], b0, b1);                              \
            }                                                                  \
        }                                                                      \
    }

template<int NCH>
__device__ __forceinline__ void gemm_tc(const float* __restrict__ A,
                                        const float* __restrict__ W,
                                        int C, int j0, int k0,
                                        float* __restrict__ outp,
                                        float* sm) {
    float* As0 = sm;
    float* As1 = sm + 1152;
    float* Ws0 = sm + 2304;
    float* Ws1 = sm + 2304 + 4608;
    int tid = threadIdx.x;
    int wid = tid >> 5, lane = tid & 31;
    int r = lane >> 2, q = lane & 3;

    stage_chunk(As0, Ws0, A, W, j0, k0, tid);
    stage_chunk(As1, Ws1, A, W, j0, k0 + 32, tid);

    float acc[2][4][4];
#pragma unroll
    for (int mt = 0; mt < 2; mt++)
#pragma unroll
        for (int nt = 0; nt < 4; nt++)
#pragma unroll
            for (int i = 0; i < 4; i++) acc[mt][nt][i] = 0.f;

#pragma unroll
    for (int c = 0; c < NCH; c++) {
        if (c + 1 < NCH) cp_wait<1>(); else cp_wait<0>();
        __syncthreads();
        const float* as = (c & 1) ? As1 : As0;
        const float* ws = (c & 1) ? Ws1 : Ws0;
        MMA_CHUNK_BODY(as, ws);
        if (c + 2 < NCH) {
            __syncthreads();
            stage_chunk((c & 1) ? As1 : As0, (c & 1) ? Ws1 : Ws0,
                        A, W, j0, k0 + (c + 2) * 32, tid);
        }
    }
#pragma unroll
    for (int mt = 0; mt < 2; mt++) {
#pragma unroll
        for (int nt = 0; nt < 4; nt++) {
            int col = j0 + wid * 32 + nt * 8 + 2 * q;
            int row0 = mt * 16 + r;
            *(float2*)(outp + (size_t)row0 * C + col) =
                make_float2(acc[mt][nt][0], acc[mt][nt][1]);
            *(float2*)(outp + (size_t)(row0 + 8) * C + col) =
                make_float2(acc[mt][nt][2], acc[mt][nt][3]);
        }
    }
}

// Full-K=1024 tf32 GEMM, output stride C.
// tmode=1: output layout [n][col][l] (coalesced via smem staging).
// bias != nullptr: add bias[col] (tmode 0 only).
__device__ void gemm_tc_long(const float* __restrict__ A,
                             const float* __restrict__ W,
                             int C, int j0, int rbase, int tmode,
                             const float* __restrict__ bias,
                             float* __restrict__ outp,
                             float* sm) {
    float* As0 = sm;
    float* As1 = sm + 1152;
    float* Ws0 = sm + 2304;
    float* Ws1 = sm + 2304 + 4608;
    int tid = threadIdx.x;
    int wid = tid >> 5, lane = tid & 31;
    int r = lane >> 2, q = lane & 3;

    stage_chunk(As0, Ws0, A, W, j0, 0, tid);
    stage_chunk(As1, Ws1, A, W, j0, 32, tid);

    float acc[2][4][4];
#pragma unroll
    for (int mt = 0; mt < 2; mt++)
#pragma unroll
        for (int nt = 0; nt < 4; nt++)
#pragma unroll
            for (int i = 0; i < 4; i++) acc[mt][nt][i] = 0.f;

    for (int c = 0; c < 32; c++) {
        if (c + 1 < 32) cp_wait<1>(); else cp_wait<0>();
        __syncthreads();
        const float* as = (c & 1) ? As1 : As0;
        const float* ws = (c & 1) ? Ws1 : Ws0;
        MMA_CHUNK_BODY(as, ws);
        if (c + 2 < 32) {
            __syncthreads();
            stage_chunk((c & 1) ? As1 : As0, (c & 1) ? Ws1 : Ws0,
                        A, W, j0, (c + 2) * 32, tid);
        }
    }

    if (tmode == 0) {
#pragma unroll
        for (int mt = 0; mt < 2; mt++) {
#pragma unroll
            for (int nt = 0; nt < 4; nt++) {
                int col = j0 + wid * 32 + nt * 8 + 2 * q;
#pragma unroll
                for (int hr = 0; hr < 2; hr++) {
                    int rl = mt * 16 + r + hr * 8;
                    float v0 = acc[mt][nt][hr * 2 + 0];
                    float v1 = acc[mt][nt][hr * 2 + 1];
                    if (bias) { v0 += bias[col]; v1 += bias[col + 1]; }
                    *(float2*)(outp + (size_t)rl * C + col) = make_float2(v0, v1);
                }
            }
        }
    } else {
        // stage 32x128 tile in smem (stride 129), then coalesced [n][col][l]
        __syncthreads();
        float* st = sm;   // 32*129 = 4128 floats
#pragma unroll
        for (int mt = 0; mt < 2; mt++) {
#pragma unroll
            for (int nt = 0; nt < 4; nt++) {
                int coll = wid * 32 + nt * 8 + 2 * q;
#pragma unroll
                for (int hr = 0; hr < 2; hr++) {
                    int rl = mt * 16 + r + hr * 8;
                    st[rl * 129 + coll]     = acc[mt][nt][hr * 2 + 0];
                    st[rl * 129 + coll + 1] = acc[mt][nt][hr * 2 + 1];
                }
            }
        }
        __syncthreads();
        int n = rbase >> 6;
        int l0 = rbase & 63;        // 0 or 32
        int l = tid & 31;
        int c0 = tid >> 5;          // 0..3
#pragma unroll
        for (int it = 0; it < 32; it++) {
            int col = c0 + it * 4;
            outp[((size_t)n * G3 + j0 + col) * 64 + l0 + l] = st[l * 129 + col];
        }
    }
}

// ---------------------------------------------------------------------------
// P2: attention scores. 256 blocks: n = b&31, lg = b>>5 (8 l each)
// ---------------------------------------------------------------------------
__device__ __forceinline__ void score_body(int b, const float* __restrict__ v_att,
                                           float* sm) {
    float* sdec = sm;
    float* sv   = sm + 1024;
    int n = b & 31, lg = b >> 5;
    int tid = threadIdx.x;
    for (int i = tid; i < 1024; i += 128) {
        float s = 0.f;
#pragma unroll
        for (int sp = 0; sp < 8; sp++)
            s += g_dp_part[((size_t)sp * NB + n) * 1024 + i];
        sdec[i] = s;
        sv[i] = v_att[i];
    }
    __syncthreads();
    int w = tid >> 5, lane = tid & 31;
#pragma unroll
    for (int li = 0; li < 2; li++) {
        int l = lg * 8 + w * 2 + li;
        const float* ep = g_enc_proj + ((size_t)n * 64 + l) * 1024;
        float s = 0.f;
        for (int a = lane; a < 1024; a += 32)
            s += tanh_fast(ep[a] + sdec[a]) * sv[a];
#pragma unroll
        for (int o = 16; o; o >>= 1) s += __shfl_xor_sync(0xffffffffu, s, o);
        if (lane == 0) g_score[n * 64 + l] = s;
    }
}

// ---------------------------------------------------------------------------
// P3: softmax + gi0 (att@encWih0T + precomp0) + combine0 -> h0
// ---------------------------------------------------------------------------
__device__ __forceinline__ void gi0comb_body(int b, int t,
                                             const float* __restrict__ b_ih,
                                             const float* __restrict__ b_hh,
                                             float* __restrict__ out,
                                             float* sm) {
    float* satt = sm;
    int n = b & 31, jg = b >> 5;
    int tid = threadIdx.x;
    if (tid < 32) {
        float a0 = g_score[n * 64 + tid], a1 = g_score[n * 64 + tid + 32];
        float m = fmaxf(a0, a1);
#pragma unroll
        for (int o = 16; o; o >>= 1) m = fmaxf(m, __shfl_xor_sync(0xffffffffu, m, o));
        float e0 = __expf(a0 - m), e1 = __expf(a1 - m);
        float sum = e0 + e1;
#pragma unroll
        for (int o = 16; o; o >>= 1) sum += __shfl_xor_sync(0xffffffffu, sum, o);
        float inv = 1.f / sum;
        satt[tid]      = e0 * inv;
        satt[tid + 32] = e1 * inv;
        if (jg == 0) {
            out[ATT_BASE + ((size_t)n * 64 + tid)      * TSTEP + t] = e0 * inv;
            out[ATT_BASE + ((size_t)n * 64 + tid + 32) * TSTEP + t] = e1 * inv;
        }
    }
    __syncthreads();

    int j = jg * 128 + tid;
    const float* base = g_encWih0T + (size_t)n * G3 * 64;
    const float4* pr = (const float4*)(base + (size_t)j * 64);
    const float4* pz = (const float4*)(base + (size_t)(1024 + j) * 64);
    const float4* pn = (const float4*)(base + (size_t)(2048 + j) * 64);
    float dr = 0.f, dz = 0.f, dn = 0.f;
#pragma unroll
    for (int lq = 0; lq < 16; lq++) {
        float a0 = satt[lq * 4 + 0], a1 = satt[lq * 4 + 1];
        float a2 = satt[lq * 4 + 2], a3 = satt[lq * 4 + 3];
        float4 vr = pr[lq], vz = pz[lq], vn = pn[lq];
        dr += a0 * vr.x + a1 * vr.y + a2 * vr.z + a3 * vr.w;
        dz += a0 * vz.x + a1 * vz.y + a2 * vz.z + a3 * vz.w;
        dn += a0 * vn.x + a1 * vn.y + a2 * vn.z + a3 * vn.w;
    }
    const float* pc = g_precomp0 + ((size_t)t * NB + n) * G3;
    float gir = pc[j]        + dr + b_ih[j];
    float giz = pc[1024 + j] + dz + b_ih[1024 + j];
    float gin = pc[2048 + j] + dn + b_ih[2048 + j];
    float ghr = b_hh[j], ghz = b_hh[1024 + j], ghn = b_hh[2048 + j];
#pragma unroll
    for (int s = 0; s < 8; s++) {
        const float* gp = g_gh0_part + ((size_t)s * NB + n) * G3;
        ghr += gp[j]; ghz += gp[1024 + j]; ghn += gp[2048 + j];
    }
    float rr = 1.f / (1.f + expf(-(gir + ghr)));
    float zz = 1.f / (1.f + expf(-(giz + ghz)));
    float nn = tanhf(gin + rr * ghn);
    float* h0 = g_h + n * HID;
    h0[j] = (1.f - zz) * nn + zz * h0[j];
}

// ---------------------------------------------------------------------------
// comb1: 8 gi + 8 gh parts + biases -> h1 + dec_hids out
// ---------------------------------------------------------------------------
__device__ __forceinline__ void add4(float* a, float4 v) {
    a[0] += v.x; a[1] += v.y; a[2] += v.z; a[3] += v.w;
}

__device__ __forceinline__ void combine1_body(int t, int n,
                                              const float* __restrict__ b_ih_l,
                                              const float* __restrict__ b_hh_l,
                                              float* __restrict__ out_hid) {
    int tid = threadIdx.x;
    float* h = g_h + NB * HID + n * HID;
#pragma unroll
    for (int half = 0; half < 2; half++) {
        int j = tid * 4 + half * 512;
        float gi[3][4] = {}, gh[3][4] = {};
#pragma unroll
        for (int g = 0; g < 3; g++) {
#pragma unroll
            for (int s = 0; s < 8; s++) {
                add4(gi[g], *(const float4*)(g_gi_part  + ((size_t)s * NB + n) * G3 + g * 1024 + j));
                add4(gh[g], *(const float4*)(g_gh1_part + ((size_t)s * NB + n) * G3 + g * 1024 + j));
            }
            add4(gi[g], *(const float4*)(b_ih_l + g * 1024 + j));
            add4(gh[g], *(const float4*)(b_hh_l + g * 1024 + j));
        }
        float4 ho = *(const float4*)(h + j);
        float ho_[4] = {ho.x, ho.y, ho.z, ho.w};
        float hn_[4];
#pragma unroll
        for (int c = 0; c < 4; c++) {
            float r  = 1.f / (1.f + expf(-(gi[0][c] + gh[0][c])));
            float z  = 1.f / (1.f + expf(-(gi[1][c] + gh[1][c])));
            float nn = tanhf(gi[2][c] + r * gh[2][c]);
            hn_[c] = (1.f - z) * nn + z * ho_[c];
        }
        float4 hv = {hn_[0], hn_[1], hn_[2], hn_[3]};
        *(float4*)(h + j) = hv;
        *(float4*)(out_hid + ((size_t)n * TSTEP + t) * 1024 + j) = hv;
    }
}

// ---------------------------------------------------------------------------
// Persistent decode kernel: 5 grid barriers per step
// ---------------------------------------------------------------------------
__global__ void __launch_bounds__(128) decode_kernel(
        const float* __restrict__ dec_init,
        const float* __restrict__ W_att_dec,
        const float* __restrict__ W_hh,
        const float* __restrict__ W_ih,
        const float* __restrict__ b_ih,
        const float* __restrict__ b_hh,
        const float* __restrict__ v_att,
        float* __restrict__ out) {
    __shared__ float sm[11520];
    int b = blockIdx.x;
    int tid = threadIdx.x;
    unsigned ph = 0;

    if (b < 32) {
        for (int i = b * 128 + tid; i < 2 * NB * HID; i += 32 * 128)
            g_h[i] = dec_init[i];
    } else if (b >= 64) {
        int x = b - 64;
        int tile = x >> 3, split = x & 7;
        gemm_tc<4>(dec_init, W_hh, G3, tile * 128, split * 128,
                   g_gh0_part + (size_t)split * NB * G3, sm);
    }
    gridbar(++ph);

    for (int t = 0; t < TSTEP; t++) {
        if (b < 64) {
            int tile = b >> 3, split = b & 7;
            gemm_tc<4>(g_h + NB * HID, W_att_dec, 1024, tile * 128, split * 128,
                       g_dp_part + (size_t)split * NB * 1024, sm);
        } else {
            int x = b - 64;
            int tile = x >> 3, split = x & 7;
            gemm_tc<4>(g_h + NB * HID, W_hh + (size_t)G3 * 1024, G3, tile * 128,
                       split * 128, g_gh1_part + (size_t)split * NB * G3, sm);
        }
        gridbar(++ph);

        score_body(b, v_att, sm);
        gridbar(++ph);

        gi0comb_body(b, t, b_ih, b_hh, out, sm);
        gridbar(++ph);

        if (b < 192) {
            int tile = b >> 3, split = b & 7;
            gemm_tc<4>(g_h, W_ih + (size_t)G3 * 1024, G3, tile * 128, split * 128,
                       g_gi_part + (size_t)split * NB * G3, sm);
        }
        gridbar(++ph);

        if (b < 32) {
            combine1_body(t, b, b_ih + G3, b_hh + G3, out);
        } else if (b >= 64) {
            int x = b - 64;
            int tile = x >> 3, split = x & 7;
            gemm_tc<4>(g_h, W_hh, G3, tile * 128, split * 128,
                       g_gh0_part + (size_t)split * NB * G3, sm);
        }
        gridbar(++ph);
    }

    for (int i = b * 128 + tid; i < 2 * NB * HID; i += NBLK * 128)
        out[DECPREV_BASE + i] = g_h[i];
}

// ---------------------------------------------------------------------------
// Prologue 0: embedding gather + bias precompute + barrier reset
// ---------------------------------------------------------------------------
__global__ void prol_setup(const int* __restrict__ input_ids,
                           const float* __restrict__ emb_table,
                           const float* __restrict__ b_in,
                           const float* __restrict__ b_ctx) {
    int b = blockIdx.x, tid = threadIdx.x;
    if (b < TSTEP * NB) {
        int t = b >> 5, n = b & 31;
        int id = input_ids[n * 64 + t];
        float4 v = *(const float4*)(emb_table + (size_t)id * 1024 + tid * 4);
        *(float4*)(g_emb_src + (size_t)b * 1024 + tid * 4) = v;
    } else {
        float4 bi = *(const float4*)(b_in + tid * 4);
        float4 bc = *(const float4*)(b_ctx + tid * 4);
        *(float4*)(g_bias + tid * 4) =
            make_float4(bi.x + bc.x, bi.y + bc.y, bi.z + bc.z, bi.w + bc.w);
        if (tid == 0) { g_master = 0; g_gen2 = 0; }
        if (tid < NLEAF) g_leaf[tid * 32] = 0;
    }
}

// ---------------------------------------------------------------------------
// Prologue 1 (fp32): enc_proj only. 512 x 256.
// ---------------------------------------------------------------------------
__global__ void prol_fp32(const float* __restrict__ enc_hids,
                          const float* __restrict__ W_att_enc) {
    __shared__ float As[2][32 * 68];
    __shared__ float Ws[2][32 * 68];
    int b = blockIdx.x;
    int rt = b >> 4, ct = b & 15;
    int r0 = rt * 64, c0 = ct * 64;
    int tid = threadIdx.x;
    int lp = tid & 7, lr = tid >> 3;
    int tx = tid & 15, ty = tid >> 4;
    const float* W = W_att_enc;

    float4 a[2], wv[2];
#define PROL_FETCH(k0)                                                          \
    {                                                                           \
        _Pragma("unroll")                                                       \
        for (int h = 0; h < 2; h++) {                                           \
            int gr = r0 + lr + h * 32;                                          \
            a[h] = *(const float4*)(enc_hids + (size_t)gr * 1024 + (k0) + lp * 4); \
            wv[h] = *(const float4*)(W + (size_t)(c0 + lr + h * 32) * 1024 + (k0) + lp * 4); \
        }                                                                       \
    }
#define PROL_STORE(buf)                                                         \
    {                                                                           \
        _Pragma("unroll")                                                       \
        for (int h = 0; h < 2; h++) {                                           \
            int rr = lr + h * 32;                                               \
            As[buf][(lp * 4 + 0) * 68 + rr] = a[h].x;                           \
            As[buf][(lp * 4 + 1) * 68 + rr] = a[h].y;                           \
            As[buf][(lp * 4 + 2) * 68 + rr] = a[h].z;                           \
            As[buf][(lp * 4 + 3) * 68 + rr] = a[h].w;                           \
            Ws[buf][(lp * 4 + 0) * 68 + rr] = wv[h].x;                          \
            Ws[buf][(lp * 4 + 1) * 68 + rr] = wv[h].y;                          \
            Ws[buf][(lp * 4 + 2) * 68 + rr] = wv[h].z;                          \
            Ws[buf][(lp * 4 + 3) * 68 + rr] = wv[h].w;                          \
        }                                                                       \
    }

    float acc[4][4];
#pragma unroll
    for (int i = 0; i < 4; i++)
#pragma unroll
        for (int j = 0; j < 4; j++) acc[i][j] = 0.f;

    PROL_FETCH(0);
    PROL_STORE(0);
    __syncthreads();
    for (int c = 0; c < 32; c++) {
        const float* as = As[c & 1];
        const float* ws = Ws[c & 1];
        if (c + 1 < 32) PROL_FETCH((c + 1) * 32);
#pragma unroll
        for (int kk = 0; kk < 32; kk++) {
            float4 a4 = *(const float4*)&as[kk * 68 + ty * 4];
            float4 b4 = *(const float4*)&ws[kk * 68 + tx * 4];
            float avv[4] = {a4.x, a4.y, a4.z, a4.w};
            float bvv[4] = {b4.x, b4.y, b4.z, b4.w};
#pragma unroll
            for (int i = 0; i < 4; i++)
#pragma unroll
                for (int j = 0; j < 4; j++) acc[i][j] += avv[i] * bvv[j];
        }
        if (c + 1 < 32) {
            PROL_STORE((c + 1) & 1);
            __syncthreads();
        }
    }
#pragma unroll
    for (int i = 0; i < 4; i++) {
        int rr = r0 + ty * 4 + i;
#pragma unroll
        for (int j = 0; j < 4; j++) {
            int cc = c0 + tx * 4 + j;
            g_enc_proj[(size_t)rr * 1024 + cc] = acc[i][j];
        }
    }
#undef PROL_FETCH
#undef PROL_STORE
}

// ---------------------------------------------------------------------------
// Prologue 2 (tf32): encW (512 blocks) + emb_merged (+bias, 504 blocks)
// ---------------------------------------------------------------------------
__global__ void __launch_bounds__(128) prol_tc1(const float* __restrict__ enc_hids,
                                                const float* __restrict__ W_ctx,
                                                const float* __restrict__ W_in) {
    __shared__ float sm[11520];
    int b = blockIdx.x;
    if (b < 512) {
        int rt = b >> 3, ct = b & 7;
        gemm_tc_long(enc_hids + (size_t)rt * 32 * 1024, W_ctx, 1024, ct * 128,
                     0, 0, nullptr, g_encW + (size_t)rt * 32 * 1024, sm);
    } else {
        int x = b - 512;
        int rt = x >> 3, ct = x & 7;
        gemm_tc_long(g_emb_src + (size_t)rt * 32 * 1024, W_in, 1024, ct * 128,
                     0, 0, g_bias, g_emb_merged + (size_t)rt * 32 * 1024, sm);
    }
}

// ---------------------------------------------------------------------------
// Prologue 3 (tf32): encWih0T (transposed, coalesced) + precomp0. 3048 x 128.
// ---------------------------------------------------------------------------
__global__ void __launch_bounds__(128) prol_tc2(const float* __restrict__ W_ih) {
    __shared__ float sm[11520];
    int b = blockIdx.x;
    if (b < 1536) {
        int rt = b / 24, ct = b % 24;
        gemm_tc_long(g_encW + (size_t)rt * 32 * 1024, W_ih, G3,
                     ct * 128, rt * 32, 1, nullptr, g_encWih0T, sm);
    } else {
        int x = b - 1536;
        int rt = x / 24, ct = x % 24;
        gemm_tc_long(g_emb_merged + (size_t)rt * 32 * 1024, W_ih, G3,
                     ct * 128, 0, 0, nullptr,
                     g_precomp0 + (size_t)rt * NB * G3, sm);
    }
}

// ---------------------------------------------------------------------------
extern "C" void kernel_launch(void* const* d_in, const int* in_sizes, int n_in,
                              void* d_out, int out_size) {
    const int*   input_ids = (const int*)  d_in[0];
    const float* dec_init  = (const float*)d_in[1];
    const float* enc_hids  = (const float*)d_in[2];
    const float* emb_table = (const float*)d_in[3];
    const float* W_in      = (const float*)d_in[4];
    const float* b_in      = (const float*)d_in[5];
    const float* W_ctx     = (const float*)d_in[6];
    const float* b_ctx     = (const float*)d_in[7];
    const float* W_att_dec = (const float*)d_in[8];
    const float* W_att_enc = (const float*)d_in[9];
    const float* v_att     = (const float*)d_in[10];
    const float* W_ih      = (const float*)d_in[11];
    const float* W_hh      = (const float*)d_in[12];
    const float* b_ih      = (const float*)d_in[13];
    const float* b_hh      = (const float*)d_in[14];
    float* out = (float*)d_out;

    prol_setup<<<TSTEP * NB + 1, 256>>>(input_ids, emb_table, b_in, b_ctx);
    prol_fp32<<<512, 256>>>(enc_hids, W_att_enc);
    prol_tc1<<<1016, 128>>>(enc_hids, W_ctx, W_in);
    prol_tc2<<<3048, 128>>>(W_ih);
    decode_kernel<<<NBLK, 128>>>(dec_init, W_att_dec, W_hh, W_ih,
                                 b_ih, b_hh, v_att, out);
}

// round 15
// speedup vs baseline: 1.1197x; 1.1197x over previous
#include <cuda_runtime.h>
#include <cuda_bf16.h>
#include <math.h>
#include <stdint.h>

#define NB    32
#define HID   1024
#define TSTEP 63
#define ENCL  64
#define G3    3072
#define PADK  36
#define NBLK  256

#define DEC_HIDS_ELEMS (NB * TSTEP * HID)
#define ATTS_ELEMS     (NB * ENCL * TSTEP)
#define ATT_BASE       DEC_HIDS_ELEMS
#define DECPREV_BASE   (DEC_HIDS_ELEMS + ATTS_ELEMS)

// ---------------------------------------------------------------------------
// Scratch (row-padded to 2048 for M=64 tiles)
// ---------------------------------------------------------------------------
__device__ float g_enc_proj[NB * ENCL * 1024];      // enc @ W_att_enc^T (fp32)
__device__ float g_encW    [NB * ENCL * 1024];      // enc @ W_ctx^T (tf32)
__device__ float g_emb_src [2048 * 1024];           // gathered embeddings (padded)
__device__ float g_emb_merged[2048 * 1024];         // emb@W_in^T + biases (padded)
__device__ float g_bias[1024];                      // b_in + b_ctx
__device__ float g_encWih0T[NB * G3 * ENCL];        // [n][jfull][l] (tf32)
__device__ float g_precomp0[2048 * G3];             // emb_merged @ W_ih0^T (padded)

__device__ float g_h[2 * NB * HID];
__device__ float g_score[NB * ENCL];

__device__ float g_dp_part [8 * NB * HID];
__device__ float g_gh0_part[8 * NB * G3];
__device__ float g_gh1_part[8 * NB * G3];
__device__ float g_gi_part [8 * NB * G3];

__device__ unsigned g_bar_cnt;
__device__ unsigned g_bar_gen;

// ---------------------------------------------------------------------------
// Helpers
// ---------------------------------------------------------------------------
__device__ __forceinline__ float tanh_fast(float x) {
    float y;
    asm("tanh.approx.f32 %0, %1;" : "=f"(y) : "f"(x));
    return y;
}
__device__ __forceinline__ uint32_t f2tf(float x) {
    uint32_t r;
    asm("cvt.rna.tf32.f32 %0, %1;" : "=r"(r) : "f"(x));
    return r;
}
__device__ __forceinline__ void mma8(float* d, const uint32_t* a,
                                     uint32_t b0, uint32_t b1) {
    asm volatile(
        "mma.sync.aligned.m16n8k8.row.col.f32.tf32.tf32.f32 "
        "{%0,%1,%2,%3}, {%4,%5,%6,%7}, {%8,%9}, {%0,%1,%2,%3};"
        : "+f"(d[0]), "+f"(d[1]), "+f"(d[2]), "+f"(d[3])
        : "r"(a[0]), "r"(a[1]), "r"(a[2]), "r"(a[3]), "r"(b0), "r"(b1));
}
__device__ __forceinline__ void cp16(void* smem_dst, const void* gsrc) {
    unsigned s = (unsigned)__cvta_generic_to_shared(smem_dst);
    asm volatile("cp.async.ca.shared.global [%0], [%1], 16;" :: "r"(s), "l"(gsrc));
}
__device__ __forceinline__ void cp_commit() {
    asm volatile("cp.async.commit_group;");
}
template<int N> __device__ __forceinline__ void cp_wait() {
    asm volatile("cp.async.wait_group %0;" :: "n"(N));
}

// CG-style grid barrier (release-arrive + acquire-spin). R13 version.
__device__ __forceinline__ void gridbar() {
    __syncthreads();
    if (threadIdx.x == 0) {
        unsigned* cnt = &g_bar_cnt;
        unsigned* gen = &g_bar_gen;
        unsigned my;
        asm volatile("ld.relaxed.gpu.u32 %0, [%1];" : "=r"(my) : "l"(gen));
        unsigned old;
        asm volatile("atom.add.acq_rel.gpu.u32 %0, [%1], 1;"
                     : "=r"(old) : "l"(cnt) : "memory");
        if (old == NBLK - 1) {
            asm volatile("st.relaxed.gpu.u32 [%0], %1;" :: "l"(cnt), "r"(0u) : "memory");
            asm volatile("red.release.gpu.add.u32 [%0], %1;" :: "l"(gen), "r"(1u) : "memory");
        } else {
            unsigned g;
            do {
                asm volatile("ld.acquire.gpu.u32 %0, [%1];"
                             : "=r"(g) : "l"(gen) : "memory");
            } while (g == my);
        }
    }
    __syncthreads();
}

// ---------------------------------------------------------------------------
// tf32 tc GEMM (M=32): out[32 x 128cols @j0] = A[32 x (NCH*32)k @k0] @ W^T
// ---------------------------------------------------------------------------
__device__ __forceinline__ void stage_chunk(float* Asb, float* Wsb,
                                            const float* __restrict__ A,
                                            const float* __restrict__ W,
                                            int j0, int kg, int tid) {
#pragma unroll
    for (int i = 0; i < 2; i++) {
        int idx = tid + i * 128;
        int row = idx >> 3, seg = idx & 7;
        cp16(Asb + row * PADK + seg * 4, A + (size_t)row * 1024 + kg + seg * 4);
    }
#pragma unroll
    for (int i = 0; i < 8; i++) {
        int idx = tid + i * 128;
        int row = idx >> 3, seg = idx & 7;
        cp16(Wsb + row * PADK + seg * 4, W + (size_t)(j0 + row) * 1024 + kg + seg * 4);
    }
    cp_commit();
}

#define MMA_CHUNK_BODY(as, ws)                                                 \
    {                                                                          \
        _Pragma("unroll")                                                      \
        for (int ks = 0; ks < 4; ks++) {                                       \
            int kq = ks * 8 + q;                                               \
            uint32_t afr[2][4];                                                \
            _Pragma("unroll")                                                  \
            for (int mt = 0; mt < 2; mt++) {                                   \
                afr[mt][0] = f2tf((as)[(mt * 16 + r)     * PADK + kq]);        \
                afr[mt][1] = f2tf((as)[(mt * 16 + r + 8) * PADK + kq]);        \
                afr[mt][2] = f2tf((as)[(mt * 16 + r)     * PADK + kq + 4]);    \
                afr[mt][3] = f2tf((as)[(mt * 16 + r + 8) * PADK + kq + 4]);    \
            }                                                                  \
            _Pragma("unroll")                                                  \
            for (int nt = 0; nt < 4; nt++) {                                   \
                int n = wid * 32 + nt * 8 + r;                                 \
                uint32_t b0 = f2tf((ws)[n * PADK + ks * 8 + q]);               \
                uint32_t b1 = f2tf((ws)[n * PADK + ks * 8 + 4 + q]);           \
                mma8(acc[0][nt], afr[0], b0, b1);                              \
                mma8(acc[1][nt], afr[1], b0, b1);                              \
            }                                                                  \
        }                                                                      \
    }

template<int NCH>
__device__ __forceinline__ void gemm_tc(const float* __restrict__ A,
                                        const float* __restrict__ W,
                                        int C, int j0, int k0,
                                        float* __restrict__ outp,
                                        float* sm) {
    float* As0 = sm;
    float* As1 = sm + 1152;
    float* Ws0 = sm + 2304;
    float* Ws1 = sm + 2304 + 4608;
    int tid = threadIdx.x;
    int wid = tid >> 5, lane = tid & 31;
    int r = lane >> 2, q = lane & 3;

    stage_chunk(As0, Ws0, A, W, j0, k0, tid);
    stage_chunk(As1, Ws1, A, W, j0, k0 + 32, tid);

    float acc[2][4][4];
#pragma unroll
    for (int mt = 0; mt < 2; mt++)
#pragma unroll
        for (int nt = 0; nt < 4; nt++)
#pragma unroll
            for (int i = 0; i < 4; i++) acc[mt][nt][i] = 0.f;

#pragma unroll
    for (int c = 0; c < NCH; c++) {
        if (c + 1 < NCH) cp_wait<1>(); else cp_wait<0>();
        __syncthreads();
        const float* as = (c & 1) ? As1 : As0;
        const float* ws = (c & 1) ? Ws1 : Ws0;
        MMA_CHUNK_BODY(as, ws);
        if (c + 2 < NCH) {
            __syncthreads();
            stage_chunk((c & 1) ? As1 : As0, (c & 1) ? Ws1 : Ws0,
                        A, W, j0, k0 + (c + 2) * 32, tid);
        }
    }
#pragma unroll
    for (int mt = 0; mt < 2; mt++) {
#pragma unroll
        for (int nt = 0; nt < 4; nt++) {
            int col = j0 + wid * 32 + nt * 8 + 2 * q;
            int row0 = mt * 16 + r;
            *(float2*)(outp + (size_t)row0 * C + col) =
                make_float2(acc[mt][nt][0], acc[mt][nt][1]);
            *(float2*)(outp + (size_t)(row0 + 8) * C + col) =
                make_float2(acc[mt][nt][2], acc[mt][nt][3]);
        }
    }
}

// ---------------------------------------------------------------------------
// M=64 full-K=1024 tf32 GEMM for the prologue. 2x flops per staged W byte.
// tmode=1: output [n][col][l] coalesced (one n per 64-row tile, rbase=n*64).
// ---------------------------------------------------------------------------
__device__ __forceinline__ void stage_chunk64(float* Asb, float* Wsb,
                                              const float* __restrict__ A,
                                              const float* __restrict__ W,
                                              int j0, int kg, int tid) {
#pragma unroll
    for (int i = 0; i < 4; i++) {
        int idx = tid + i * 128;
        int row = idx >> 3, seg = idx & 7;
        cp16(Asb + row * PADK + seg * 4, A + (size_t)row * 1024 + kg + seg * 4);
    }
#pragma unroll
    for (int i = 0; i < 8; i++) {
        int idx = tid + i * 128;
        int row = idx >> 3, seg = idx & 7;
        cp16(Wsb + row * PADK + seg * 4, W + (size_t)(j0 + row) * 1024 + kg + seg * 4);
    }
    cp_commit();
}

__device__ void gemm_tc_long64(const float* __restrict__ A,
                               const float* __restrict__ W,
                               int C, int j0, int rbase, int tmode,
                               const float* __restrict__ bias,
                               float* __restrict__ outp,
                               float* sm) {
    float* As0 = sm;                    // 64*36 = 2304
    float* As1 = sm + 2304;
    float* Ws0 = sm + 4608;             // 128*36 = 4608
    float* Ws1 = sm + 4608 + 4608;
    int tid = threadIdx.x;
    int wid = tid >> 5, lane = tid & 31;
    int r = lane >> 2, q = lane & 3;

    stage_chunk64(As0, Ws0, A, W, j0, 0, tid);
    stage_chunk64(As1, Ws1, A, W, j0, 32, tid);

    float acc[4][4][4];
#pragma unroll
    for (int mt = 0; mt < 4; mt++)
#pragma unroll
        for (int nt = 0; nt < 4; nt++)
#pragma unroll
            for (int i = 0; i < 4; i++) acc[mt][nt][i] = 0.f;

    for (int c = 0; c < 32; c++) {
        if (c + 1 < 32) cp_wait<1>(); else cp_wait<0>();
        __syncthreads();
        const float* as = (c & 1) ? As1 : As0;
        const float* ws = (c & 1) ? Ws1 : Ws0;
#pragma unroll
        for (int ks = 0; ks < 4; ks++) {
            int kq = ks * 8 + q;
            uint32_t afr[4][4];
#pragma unroll
            for (int mt = 0; mt < 4; mt++) {
                afr[mt][0] = f2tf(as[(mt * 16 + r)     * PADK + kq]);
                afr[mt][1] = f2tf(as[(mt * 16 + r + 8) * PADK + kq]);
                afr[mt][2] = f2tf(as[(mt * 16 + r)     * PADK + kq + 4]);
                afr[mt][3] = f2tf(as[(mt * 16 + r + 8) * PADK + kq + 4]);
            }
#pragma unroll
            for (int nt = 0; nt < 4; nt++) {
                int n = wid * 32 + nt * 8 + r;
                uint32_t b0 = f2tf(ws[n * PADK + ks * 8 + q]);
                uint32_t b1 = f2tf(ws[n * PADK + ks * 8 + 4 + q]);
#pragma unroll
                for (int mt = 0; mt < 4; mt++)
                    mma8(acc[mt][nt], afr[mt], b0, b1);
            }
        }
        if (c + 2 < 32) {
            __syncthreads();
            stage_chunk64((c & 1) ? As1 : As0, (c & 1) ? Ws1 : Ws0,
                          A, W, j0, (c + 2) * 32, tid);
        }
    }

    if (tmode == 0) {
#pragma unroll
        for (int mt = 0; mt < 4; mt++) {
#pragma unroll
            for (int nt = 0; nt < 4; nt++) {
                int col = j0 + wid * 32 + nt * 8 + 2 * q;
#pragma unroll
                for (int hr = 0; hr < 2; hr++) {
                    int rl = mt * 16 + r + hr * 8;
                    float v0 = acc[mt][nt][hr * 2 + 0];
                    float v1 = acc[mt][nt][hr * 2 + 1];
                    if (bias) { v0 += bias[col]; v1 += bias[col + 1]; }
                    *(float2*)(outp + (size_t)rl * C + col) = make_float2(v0, v1);
                }
            }
        }
    } else {
        // stage 64x128 tile in smem (stride 129), then coalesced [n][col][l]
        __syncthreads();
        float* st = sm;   // 64*129 = 8256 floats (fits in 13824)
#pragma unroll
        for (int mt = 0; mt < 4; mt++) {
#pragma unroll
            for (int nt = 0; nt < 4; nt++) {
                int coll = wid * 32 + nt * 8 + 2 * q;
#pragma unroll
                for (int hr = 0; hr < 2; hr++) {
                    int rl = mt * 16 + r + hr * 8;
                    st[rl * 129 + coll]     = acc[mt][nt][hr * 2 + 0];
                    st[rl * 129 + coll + 1] = acc[mt][nt][hr * 2 + 1];
                }
            }
        }
        __syncthreads();
        int n = rbase >> 6;
        int l = tid & 63;
        int c0 = tid >> 6;          // 0..1
#pragma unroll
        for (int it = 0; it < 64; it++) {
            int col = c0 + it * 2;
            outp[((size_t)n * G3 + j0 + col) * 64 + l] = st[l * 129 + col];
        }
    }
}

// ---------------------------------------------------------------------------
// P2: attention scores. 256 blocks: n = b&31, lg = b>>5 (8 l each)
// ---------------------------------------------------------------------------
__device__ __forceinline__ void score_body(int b, const float* __restrict__ v_att,
                                           float* sm) {
    float* sdec = sm;
    float* sv   = sm + 1024;
    int n = b & 31, lg = b >> 5;
    int tid = threadIdx.x;
    for (int i = tid; i < 1024; i += 128) {
        float s = 0.f;
#pragma unroll
        for (int sp = 0; sp < 8; sp++)
            s += g_dp_part[((size_t)sp * NB + n) * 1024 + i];
        sdec[i] = s;
        sv[i] = v_att[i];
    }
    __syncthreads();
    int w = tid >> 5, lane = tid & 31;
#pragma unroll
    for (int li = 0; li < 2; li++) {
        int l = lg * 8 + w * 2 + li;
        const float* ep = g_enc_proj + ((size_t)n * 64 + l) * 1024;
        float s = 0.f;
        for (int a = lane; a < 1024; a += 32)
            s += tanh_fast(ep[a] + sdec[a]) * sv[a];
#pragma unroll
        for (int o = 16; o; o >>= 1) s += __shfl_xor_sync(0xffffffffu, s, o);
        if (lane == 0) g_score[n * 64 + l] = s;
    }
}

// ---------------------------------------------------------------------------
// P3: softmax + gi0 (att@encWih0T + precomp0) + combine0 -> h0
// ---------------------------------------------------------------------------
__device__ __forceinline__ void gi0comb_body(int b, int t,
                                             const float* __restrict__ b_ih,
                                             const float* __restrict__ b_hh,
                                             float* __restrict__ out,
                                             float* sm) {
    float* satt = sm;
    int n = b & 31, jg = b >> 5;
    int tid = threadIdx.x;
    if (tid < 32) {
        float a0 = g_score[n * 64 + tid], a1 = g_score[n * 64 + tid + 32];
        float m = fmaxf(a0, a1);
#pragma unroll
        for (int o = 16; o; o >>= 1) m = fmaxf(m, __shfl_xor_sync(0xffffffffu, m, o));
        float e0 = __expf(a0 - m), e1 = __expf(a1 - m);
        float sum = e0 + e1;
#pragma unroll
        for (int o = 16; o; o >>= 1) sum += __shfl_xor_sync(0xffffffffu, sum, o);
        float inv = 1.f / sum;
        satt[tid]      = e0 * inv;
        satt[tid + 32] = e1 * inv;
        if (jg == 0) {
            out[ATT_BASE + ((size_t)n * 64 + tid)      * TSTEP + t] = e0 * inv;
            out[ATT_BASE + ((size_t)n * 64 + tid + 32) * TSTEP + t] = e1 * inv;
        }
    }
    __syncthreads();

    int j = jg * 128 + tid;
    const float* base = g_encWih0T + (size_t)n * G3 * 64;
    const float4* pr = (const float4*)(base + (size_t)j * 64);
    const float4* pz = (const float4*)(base + (size_t)(1024 + j) * 64);
    const float4* pn = (const float4*)(base + (size_t)(2048 + j) * 64);
    float dr = 0.f, dz = 0.f, dn = 0.f;
#pragma unroll
    for (int lq = 0; lq < 16; lq++) {
        float a0 = satt[lq * 4 + 0], a1 = satt[lq * 4 + 1];
        float a2 = satt[lq * 4 + 2], a3 = satt[lq * 4 + 3];
        float4 vr = pr[lq], vz = pz[lq], vn = pn[lq];
        dr += a0 * vr.x + a1 * vr.y + a2 * vr.z + a3 * vr.w;
        dz += a0 * vz.x + a1 * vz.y + a2 * vz.z + a3 * vz.w;
        dn += a0 * vn.x + a1 * vn.y + a2 * vn.z + a3 * vn.w;
    }
    const float* pc = g_precomp0 + ((size_t)t * NB + n) * G3;
    float gir = pc[j]        + dr + b_ih[j];
    float giz = pc[1024 + j] + dz + b_ih[1024 + j];
    float gin = pc[2048 + j] + dn + b_ih[2048 + j];
    float ghr = b_hh[j], ghz = b_hh[1024 + j], ghn = b_hh[2048 + j];
#pragma unroll
    for (int s = 0; s < 8; s++) {
        const float* gp = g_gh0_part + ((size_t)s * NB + n) * G3;
        ghr += gp[j]; ghz += gp[1024 + j]; ghn += gp[2048 + j];
    }
    float rr = 1.f / (1.f + expf(-(gir + ghr)));
    float zz = 1.f / (1.f + expf(-(giz + ghz)));
    float nn = tanhf(gin + rr * ghn);
    float* h0 = g_h + n * HID;
    h0[j] = (1.f - zz) * nn + zz * h0[j];
}

// ---------------------------------------------------------------------------
// comb1: 8 gi + 8 gh parts + biases -> h1 + dec_hids out
// ---------------------------------------------------------------------------
__device__ __forceinline__ void add4(float* a, float4 v) {
    a[0] += v.x; a[1] += v.y; a[2] += v.z; a[3] += v.w;
}

__device__ __forceinline__ void combine1_body(int t, int n,
                                              const float* __restrict__ b_ih_l,
                                              const float* __restrict__ b_hh_l,
                                              float* __restrict__ out_hid) {
    int tid = threadIdx.x;
    float* h = g_h + NB * HID + n * HID;
#pragma unroll
    for (int half = 0; half < 2; half++) {
        int j = tid * 4 + half * 512;
        float gi[3][4] = {}, gh[3][4] = {};
#pragma unroll
        for (int g = 0; g < 3; g++) {
#pragma unroll
            for (int s = 0; s < 8; s++) {
                add4(gi[g], *(const float4*)(g_gi_part  + ((size_t)s * NB + n) * G3 + g * 1024 + j));
                add4(gh[g], *(const float4*)(g_gh1_part + ((size_t)s * NB + n) * G3 + g * 1024 + j));
            }
            add4(gi[g], *(const float4*)(b_ih_l + g * 1024 + j));
            add4(gh[g], *(const float4*)(b_hh_l + g * 1024 + j));
        }
        float4 ho = *(const float4*)(h + j);
        float ho_[4] = {ho.x, ho.y, ho.z, ho.w};
        float hn_[4];
#pragma unroll
        for (int c = 0; c < 4; c++) {
            float r  = 1.f / (1.f + expf(-(gi[0][c] + gh[0][c])));
            float z  = 1.f / (1.f + expf(-(gi[1][c] + gh[1][c])));
            float nn = tanhf(gi[2][c] + r * gh[2][c]);
            hn_[c] = (1.f - z) * nn + z * ho_[c];
        }
        float4 hv = {hn_[0], hn_[1], hn_[2], hn_[3]};
        *(float4*)(h + j) = hv;
        *(float4*)(out_hid + ((size_t)n * TSTEP + t) * 1024 + j) = hv;
    }
}

// ---------------------------------------------------------------------------
// Persistent decode kernel: 5 grid barriers per step (R13 structure, verbatim)
// ---------------------------------------------------------------------------
__global__ void __launch_bounds__(128) decode_kernel(
        const float* __restrict__ dec_init,
        const float* __restrict__ W_att_dec,
        const float* __restrict__ W_hh,
        const float* __restrict__ W_ih,
        const float* __restrict__ b_ih,
        const float* __restrict__ b_hh,
        const float* __restrict__ v_att,
        float* __restrict__ out) {
    __shared__ float sm[11520];
    int b = blockIdx.x;
    int tid = threadIdx.x;

    if (b < 32) {
        for (int i = b * 128 + tid; i < 2 * NB * HID; i += 32 * 128)
            g_h[i] = dec_init[i];
    } else if (b >= 64) {
        int x = b - 64;
        int tile = x >> 3, split = x & 7;
        gemm_tc<4>(dec_init, W_hh, G3, tile * 128, split * 128,
                   g_gh0_part + (size_t)split * NB * G3, sm);
    }
    gridbar();

    for (int t = 0; t < TSTEP; t++) {
        if (b < 64) {
            int tile = b >> 3, split = b & 7;
            gemm_tc<4>(g_h + NB * HID, W_att_dec, 1024, tile * 128, split * 128,
                       g_dp_part + (size_t)split * NB * 1024, sm);
        } else {
            int x = b - 64;
            int tile = x >> 3, split = x & 7;
            gemm_tc<4>(g_h + NB * HID, W_hh + (size_t)G3 * 1024, G3, tile * 128,
                       split * 128, g_gh1_part + (size_t)split * NB * G3, sm);
        }
        gridbar();

        score_body(b, v_att, sm);
        gridbar();

        gi0comb_body(b, t, b_ih, b_hh, out, sm);
        gridbar();

        if (b < 192) {
            int tile = b >> 3, split = b & 7;
            gemm_tc<4>(g_h, W_ih + (size_t)G3 * 1024, G3, tile * 128, split * 128,
                       g_gi_part + (size_t)split * NB * G3, sm);
        }
        gridbar();

        if (b < 32) {
            combine1_body(t, b, b_ih + G3, b_hh + G3, out);
        } else if (b >= 64) {
            int x = b - 64;
            int tile = x >> 3, split = x & 7;
            gemm_tc<4>(g_h, W_hh, G3, tile * 128, split * 128,
                       g_gh0_part + (size_t)split * NB * G3, sm);
        }
        gridbar();
    }

    for (int i = b * 128 + tid; i < 2 * NB * HID; i += NBLK * 128)
        out[DECPREV_BASE + i] = g_h[i];
}

// ---------------------------------------------------------------------------
// Prologue 0: embedding gather + bias precompute + barrier reset
// ---------------------------------------------------------------------------
__global__ void prol_setup(const int* __restrict__ input_ids,
                           const float* __restrict__ emb_table,
                           const float* __restrict__ b_in,
                           const float* __restrict__ b_ctx) {
    int b = blockIdx.x, tid = threadIdx.x;
    if (b < TSTEP * NB) {
        int t = b >> 5, n = b & 31;
        int id = input_ids[n * 64 + t];
        float4 v = *(const float4*)(emb_table + (size_t)id * 1024 + tid * 4);
        *(float4*)(g_emb_src + (size_t)b * 1024 + tid * 4) = v;
    } else {
        float4 bi = *(const float4*)(b_in + tid * 4);
        float4 bc = *(const float4*)(b_ctx + tid * 4);
        *(float4*)(g_bias + tid * 4) =
            make_float4(bi.x + bc.x, bi.y + bc.y, bi.z + bc.z, bi.w + bc.w);
        if (tid == 0) { g_bar_cnt = 0; g_bar_gen = 0; }
    }
}

// ---------------------------------------------------------------------------
// Prologue 1 (fp32): enc_proj only. 512 x 256.
// ---------------------------------------------------------------------------
__global__ void prol_fp32(const float* __restrict__ enc_hids,
                          const float* __restrict__ W_att_enc) {
    __shared__ float As[2][32 * 68];
    __shared__ float Ws[2][32 * 68];
    int b = blockIdx.x;
    int rt = b >> 4, ct = b & 15;
    int r0 = rt * 64, c0 = ct * 64;
    int tid = threadIdx.x;
    int lp = tid & 7, lr = tid >> 3;
    int tx = tid & 15, ty = tid >> 4;
    const float* W = W_att_enc;

    float4 a[2], wv[2];
#define PROL_FETCH(k0)                                                          \
    {                                                                           \
        _Pragma("unroll")                                                       \
        for (int h = 0; h < 2; h++) {                                           \
            int gr = r0 + lr + h * 32;                                          \
            a[h] = *(const float4*)(enc_hids + (size_t)gr * 1024 + (k0) + lp * 4); \
            wv[h] = *(const float4*)(W + (size_t)(c0 + lr + h * 32) * 1024 + (k0) + lp * 4); \
        }                                                                       \
    }
#define PROL_STORE(buf)                                                         \
    {                                                                           \
        _Pragma("unroll")                                                       \
        for (int h = 0; h < 2; h++) {                                           \
            int rr = lr + h * 32;                                               \
            As[buf][(lp * 4 + 0) * 68 + rr] = a[h].x;                           \
            As[buf][(lp * 4 + 1) * 68 + rr] = a[h].y;                           \
            As[buf][(lp * 4 + 2) * 68 + rr] = a[h].z;                           \
            As[buf][(lp * 4 + 3) * 68 + rr] = a[h].w;                           \
            Ws[buf][(lp * 4 + 0) * 68 + rr] = wv[h].x;                          \
            Ws[buf][(lp * 4 + 1) * 68 + rr] = wv[h].y;                          \
            Ws[buf][(lp * 4 + 2) * 68 + rr] = wv[h].z;                          \
            Ws[buf][(lp * 4 + 3) * 68 + rr] = wv[h].w;                          \
        }                                                                       \
    }

    float acc[4][4];
#pragma unroll
    for (int i = 0; i < 4; i++)
#pragma unroll
        for (int j = 0; j < 4; j++) acc[i][j] = 0.f;

    PROL_FETCH(0);
    PROL_STORE(0);
    __syncthreads();
    for (int c = 0; c < 32; c++) {
        const float* as = As[c & 1];
        const float* ws = Ws[c & 1];
        if (c + 1 < 32) PROL_FETCH((c + 1) * 32);
#pragma unroll
        for (int kk = 0; kk < 32; kk++) {
            float4 a4 = *(const float4*)&as[kk * 68 + ty * 4];
            float4 b4 = *(const float4*)&ws[kk * 68 + tx * 4];
            float avv[4] = {a4.x, a4.y, a4.z, a4.w};
            float bvv[4] = {b4.x, b4.y, b4.z, b4.w};
#pragma unroll
            for (int i = 0; i < 4; i++)
#pragma unroll
                for (int j = 0; j < 4; j++) acc[i][j] += avv[i] * bvv[j];
        }
        if (c + 1 < 32) {
            PROL_STORE((c + 1) & 1);
            __syncthreads();
        }
    }
#pragma unroll
    for (int i = 0; i < 4; i++) {
        int rr = r0 + ty * 4 + i;
#pragma unroll
        for (int j = 0; j < 4; j++) {
            int cc = c0 + tx * 4 + j;
            g_enc_proj[(size_t)rr * 1024 + cc] = acc[i][j];
        }
    }
#undef PROL_FETCH
#undef PROL_STORE
}

// ---------------------------------------------------------------------------
// Prologue 2 (tf32, M=64): encW (256 blocks) + emb_merged (+bias, 256 blocks)
// ---------------------------------------------------------------------------
__global__ void __launch_bounds__(128) prol_tc1(const float* __restrict__ enc_hids,
                                                const float* __restrict__ W_ctx,
                                                const float* __restrict__ W_in) {
    __shared__ float sm[13824];
    int b = blockIdx.x;
    if (b < 256) {
        int rt = b >> 3, ct = b & 7;
        gemm_tc_long64(enc_hids + (size_t)rt * 64 * 1024, W_ctx, 1024, ct * 128,
                       0, 0, nullptr, g_encW + (size_t)rt * 64 * 1024, sm);
    } else {
        int x = b - 256;
        int rt = x >> 3, ct = x & 7;
        gemm_tc_long64(g_emb_src + (size_t)rt * 64 * 1024, W_in, 1024, ct * 128,
                       0, 0, g_bias, g_emb_merged + (size_t)rt * 64 * 1024, sm);
    }
}

// ---------------------------------------------------------------------------
// Prologue 3 (tf32, M=64): encWih0T (transposed) + precomp0. 1536 x 128.
// ---------------------------------------------------------------------------
__global__ void __launch_bounds__(128) prol_tc2(const float* __restrict__ W_ih) {
    __shared__ float sm[13824];
    int b = blockIdx.x;
    if (b < 768) {
        int rt = b / 24, ct = b % 24;      // 32 rowtiles x 24 coltiles
        gemm_tc_long64(g_encW + (size_t)rt * 64 * 1024, W_ih, G3,
                       ct * 128, rt * 64, 1, nullptr, g_encWih0T, sm);
    } else {
        int x = b - 768;
        int rt = x / 24, ct = x % 24;      // 32 rowtiles x 24 coltiles
        gemm_tc_long64(g_emb_merged + (size_t)rt * 64 * 1024, W_ih, G3,
                       ct * 128, 0, 0, nullptr,
                       g_precomp0 + (size_t)rt * 64 * G3, sm);
    }
}

// ---------------------------------------------------------------------------
extern "C" void kernel_launch(void* const* d_in, const int* in_sizes, int n_in,
                              void* d_out, int out_size) {
    const int*   input_ids = (const int*)  d_in[0];
    const float* dec_init  = (const float*)d_in[1];
    const float* enc_hids  = (const float*)d_in[2];
    const float* emb_table = (const float*)d_in[3];
    const float* W_in      = (const float*)d_in[4];
    const float* b_in      = (const float*)d_in[5];
    const float* W_ctx     = (const float*)d_in[6];
    const float* b_ctx     = (const float*)d_in[7];
    const float* W_att_dec = (const float*)d_in[8];
    const float* W_att_enc = (const float*)d_in[9];
    const float* v_att     = (const float*)d_in[10];
    const float* W_ih      = (const float*)d_in[11];
    const float* W_hh      = (const float*)d_in[12];
    const float* b_ih      = (const float*)d_in[13];
    const float* b_hh      = (const float*)d_in[14];
    float* out = (float*)d_out;

    prol_setup<<<TSTEP * NB + 1, 256>>>(input_ids, emb_table, b_in, b_ctx);
    prol_fp32<<<512, 256>>>(enc_hids, W_att_enc);
    prol_tc1<<<512, 128>>>(enc_hids, W_ctx, W_in);
    prol_tc2<<<1536, 128>>>(W_ih);
    decode_kernel<<<NBLK, 128>>>(dec_init, W_att_dec, W_hh, W_ih,
                                 b_ih, b_hh, v_att, out);
}

// round 16
// speedup vs baseline: 1.1937x; 1.0662x over previous
#include <cuda_runtime.h>
#include <cuda_bf16.h>
#include <math.h>
#include <stdint.h>

#define NB    32
#define HID   1024
#define TSTEP 63
#define ENCL  64
#define G3    3072
#define PADK  36
#define NBLK  256

#define DEC_HIDS_ELEMS (NB * TSTEP * HID)
#define ATTS_ELEMS     (NB * ENCL * TSTEP)
#define ATT_BASE       DEC_HIDS_ELEMS
#define DECPREV_BASE   (DEC_HIDS_ELEMS + ATTS_ELEMS)

// ---------------------------------------------------------------------------
// Scratch (row-padded to 2048 for M=64 tiles)
// ---------------------------------------------------------------------------
__device__ float g_enc_proj[NB * ENCL * 1024];      // enc @ W_att_enc^T (fp32)
__device__ float g_encW    [NB * ENCL * 1024];      // enc @ W_ctx^T (tf32)
__device__ float g_emb_src [2048 * 1024];           // gathered embeddings (padded)
__device__ float g_emb_merged[2048 * 1024];         // emb@W_in^T + biases (padded)
__device__ float g_bias[1024];                      // b_in + b_ctx
__device__ float g_encWih0T[NB * G3 * ENCL];        // [n][jfull][l] (tf32)
__device__ float g_precomp0[2048 * G3];             // emb_merged @ W_ih0^T (padded)

__device__ float g_h[2 * NB * HID];
__device__ float g_score[NB * ENCL];

__device__ float g_dp_part [8 * NB * HID];
__device__ float g_gh0_part[8 * NB * G3];
__device__ float g_gh1_part[8 * NB * G3];
__device__ float g_gi_part [8 * NB * G3];

__device__ unsigned g_bar_cnt;

// ---------------------------------------------------------------------------
// Helpers
// ---------------------------------------------------------------------------
__device__ __forceinline__ float tanh_fast(float x) {
    float y;
    asm("tanh.approx.f32 %0, %1;" : "=f"(y) : "f"(x));
    return y;
}
__device__ __forceinline__ uint32_t f2tf(float x) {
    uint32_t r;
    asm("cvt.rna.tf32.f32 %0, %1;" : "=r"(r) : "f"(x));
    return r;
}
__device__ __forceinline__ void mma8(float* d, const uint32_t* a,
                                     uint32_t b0, uint32_t b1) {
    asm volatile(
        "mma.sync.aligned.m16n8k8.row.col.f32.tf32.tf32.f32 "
        "{%0,%1,%2,%3}, {%4,%5,%6,%7}, {%8,%9}, {%0,%1,%2,%3};"
        : "+f"(d[0]), "+f"(d[1]), "+f"(d[2]), "+f"(d[3])
        : "r"(a[0]), "r"(a[1]), "r"(a[2]), "r"(a[3]), "r"(b0), "r"(b1));
}
__device__ __forceinline__ void cp16(void* smem_dst, const void* gsrc) {
    unsigned s = (unsigned)__cvta_generic_to_shared(smem_dst);
    asm volatile("cp.async.ca.shared.global [%0], [%1], 16;" :: "r"(s), "l"(gsrc));
}
__device__ __forceinline__ void cp_commit() {
    asm volatile("cp.async.commit_group;");
}
template<int N> __device__ __forceinline__ void cp_wait() {
    asm volatile("cp.async.wait_group %0;" :: "n"(N));
}

// Grid barrier: one release-red arrival per block; all blocks poll the
// monotonic counter against target = ph * NBLK. No release chain.
__device__ __forceinline__ void gridbar(unsigned ph) {
    __syncthreads();
    if (threadIdx.x == 0) {
        asm volatile("red.release.gpu.add.u32 [%0], %1;"
                     :: "l"(&g_bar_cnt), "r"(1u) : "memory");
        unsigned target = ph * NBLK;
        unsigned v;
        do {
            asm volatile("ld.acquire.gpu.u32 %0, [%1];"
                         : "=r"(v) : "l"(&g_bar_cnt) : "memory");
        } while (v < target);
    }
    __syncthreads();
}

// ---------------------------------------------------------------------------
// tf32 tc GEMM (M=32, KR=128, 4 chunks ALL staged upfront in 4 buffers)
// smem usage: 4*1152 + 4*4608 = 23040 floats (92160 B)
// ---------------------------------------------------------------------------
__device__ __forceinline__ void stage_chunk(float* Asb, float* Wsb,
                                            const float* __restrict__ A,
                                            const float* __restrict__ W,
                                            int j0, int kg, int tid) {
#pragma unroll
    for (int i = 0; i < 2; i++) {
        int idx = tid + i * 128;
        int row = idx >> 3, seg = idx & 7;
        cp16(Asb + row * PADK + seg * 4, A + (size_t)row * 1024 + kg + seg * 4);
    }
#pragma unroll
    for (int i = 0; i < 8; i++) {
        int idx = tid + i * 128;
        int row = idx >> 3, seg = idx & 7;
        cp16(Wsb + row * PADK + seg * 4, W + (size_t)(j0 + row) * 1024 + kg + seg * 4);
    }
    cp_commit();
}

#define MMA_CHUNK_BODY(as, ws)                                                 \
    {                                                                          \
        _Pragma("unroll")                                                      \
        for (int ks = 0; ks < 4; ks++) {                                       \
            int kq = ks * 8 + q;                                               \
            uint32_t afr[2][4];                                                \
            _Pragma("unroll")                                                  \
            for (int mt = 0; mt < 2; mt++) {                                   \
                afr[mt][0] = f2tf((as)[(mt * 16 + r)     * PADK + kq]);        \
                afr[mt][1] = f2tf((as)[(mt * 16 + r + 8) * PADK + kq]);        \
                afr[mt][2] = f2tf((as)[(mt * 16 + r)     * PADK + kq + 4]);    \
                afr[mt][3] = f2tf((as)[(mt * 16 + r + 8) * PADK + kq + 4]);    \
            }                                                                  \
            _Pragma("unroll")                                                  \
            for (int nt = 0; nt < 4; nt++) {                                   \
                int n = wid * 32 + nt * 8 + r;                                 \
                uint32_t b0 = f2tf((ws)[n * PADK + ks * 8 + q]);               \
                uint32_t b1 = f2tf((ws)[n * PADK + ks * 8 + 4 + q]);           \
                mma8(acc[0][nt], afr[0], b0, b1);                              \
                mma8(acc[1][nt], afr[1], b0, b1);                              \
            }                                                                  \
        }                                                                      \
    }

__device__ __forceinline__ void gemm_tc4(const float* __restrict__ A,
                                         const float* __restrict__ W,
                                         int C, int j0, int k0,
                                         float* __restrict__ outp,
                                         float* sm) {
    float* Asb = sm;                  // 4 x 1152
    float* Wsb = sm + 4608;           // 4 x 4608
    int tid = threadIdx.x;
    int wid = tid >> 5, lane = tid & 31;
    int r = lane >> 2, q = lane & 3;

#pragma unroll
    for (int c = 0; c < 4; c++)
        stage_chunk(Asb + c * 1152, Wsb + c * 4608, A, W, j0, k0 + c * 32, tid);

    float acc[2][4][4];
#pragma unroll
    for (int mt = 0; mt < 2; mt++)
#pragma unroll
        for (int nt = 0; nt < 4; nt++)
#pragma unroll
            for (int i = 0; i < 4; i++) acc[mt][nt][i] = 0.f;

    {
        cp_wait<3>(); __syncthreads();
        const float* as = Asb;            const float* ws = Wsb;
        MMA_CHUNK_BODY(as, ws);
    }
    {
        cp_wait<2>(); __syncthreads();
        const float* as = Asb + 1152;     const float* ws = Wsb + 4608;
        MMA_CHUNK_BODY(as, ws);
    }
    {
        cp_wait<1>(); __syncthreads();
        const float* as = Asb + 2304;     const float* ws = Wsb + 9216;
        MMA_CHUNK_BODY(as, ws);
    }
    {
        cp_wait<0>(); __syncthreads();
        const float* as = Asb + 3456;     const float* ws = Wsb + 13824;
        MMA_CHUNK_BODY(as, ws);
    }

#pragma unroll
    for (int mt = 0; mt < 2; mt++) {
#pragma unroll
        for (int nt = 0; nt < 4; nt++) {
            int col = j0 + wid * 32 + nt * 8 + 2 * q;
            int row0 = mt * 16 + r;
            *(float2*)(outp + (size_t)row0 * C + col) =
                make_float2(acc[mt][nt][0], acc[mt][nt][1]);
            *(float2*)(outp + (size_t)(row0 + 8) * C + col) =
                make_float2(acc[mt][nt][2], acc[mt][nt][3]);
        }
    }
}

// ---------------------------------------------------------------------------
// M=64 full-K=1024 tf32 GEMM for the prologue (double-buffered, R15 version)
// ---------------------------------------------------------------------------
__device__ __forceinline__ void stage_chunk64(float* Asb, float* Wsb,
                                              const float* __restrict__ A,
                                              const float* __restrict__ W,
                                              int j0, int kg, int tid) {
#pragma unroll
    for (int i = 0; i < 4; i++) {
        int idx = tid + i * 128;
        int row = idx >> 3, seg = idx & 7;
        cp16(Asb + row * PADK + seg * 4, A + (size_t)row * 1024 + kg + seg * 4);
    }
#pragma unroll
    for (int i = 0; i < 8; i++) {
        int idx = tid + i * 128;
        int row = idx >> 3, seg = idx & 7;
        cp16(Wsb + row * PADK + seg * 4, W + (size_t)(j0 + row) * 1024 + kg + seg * 4);
    }
    cp_commit();
}

__device__ void gemm_tc_long64(const float* __restrict__ A,
                               const float* __restrict__ W,
                               int C, int j0, int rbase, int tmode,
                               const float* __restrict__ bias,
                               float* __restrict__ outp,
                               float* sm) {
    float* As0 = sm;
    float* As1 = sm + 2304;
    float* Ws0 = sm + 4608;
    float* Ws1 = sm + 4608 + 4608;
    int tid = threadIdx.x;
    int wid = tid >> 5, lane = tid & 31;
    int r = lane >> 2, q = lane & 3;

    stage_chunk64(As0, Ws0, A, W, j0, 0, tid);
    stage_chunk64(As1, Ws1, A, W, j0, 32, tid);

    float acc[4][4][4];
#pragma unroll
    for (int mt = 0; mt < 4; mt++)
#pragma unroll
        for (int nt = 0; nt < 4; nt++)
#pragma unroll
            for (int i = 0; i < 4; i++) acc[mt][nt][i] = 0.f;

    for (int c = 0; c < 32; c++) {
        if (c + 1 < 32) cp_wait<1>(); else cp_wait<0>();
        __syncthreads();
        const float* as = (c & 1) ? As1 : As0;
        const float* ws = (c & 1) ? Ws1 : Ws0;
#pragma unroll
        for (int ks = 0; ks < 4; ks++) {
            int kq = ks * 8 + q;
            uint32_t afr[4][4];
#pragma unroll
            for (int mt = 0; mt < 4; mt++) {
                afr[mt][0] = f2tf(as[(mt * 16 + r)     * PADK + kq]);
                afr[mt][1] = f2tf(as[(mt * 16 + r + 8) * PADK + kq]);
                afr[mt][2] = f2tf(as[(mt * 16 + r)     * PADK + kq + 4]);
                afr[mt][3] = f2tf(as[(mt * 16 + r + 8) * PADK + kq + 4]);
            }
#pragma unroll
            for (int nt = 0; nt < 4; nt++) {
                int n = wid * 32 + nt * 8 + r;
                uint32_t b0 = f2tf(ws[n * PADK + ks * 8 + q]);
                uint32_t b1 = f2tf(ws[n * PADK + ks * 8 + 4 + q]);
#pragma unroll
                for (int mt = 0; mt < 4; mt++)
                    mma8(acc[mt][nt], afr[mt], b0, b1);
            }
        }
        if (c + 2 < 32) {
            __syncthreads();
            stage_chunk64((c & 1) ? As1 : As0, (c & 1) ? Ws1 : Ws0,
                          A, W, j0, (c + 2) * 32, tid);
        }
    }

    if (tmode == 0) {
#pragma unroll
        for (int mt = 0; mt < 4; mt++) {
#pragma unroll
            for (int nt = 0; nt < 4; nt++) {
                int col = j0 + wid * 32 + nt * 8 + 2 * q;
#pragma unroll
                for (int hr = 0; hr < 2; hr++) {
                    int rl = mt * 16 + r + hr * 8;
                    float v0 = acc[mt][nt][hr * 2 + 0];
                    float v1 = acc[mt][nt][hr * 2 + 1];
                    if (bias) { v0 += bias[col]; v1 += bias[col + 1]; }
                    *(float2*)(outp + (size_t)rl * C + col) = make_float2(v0, v1);
                }
            }
        }
    } else {
        __syncthreads();
        float* st = sm;
#pragma unroll
        for (int mt = 0; mt < 4; mt++) {
#pragma unroll
            for (int nt = 0; nt < 4; nt++) {
                int coll = wid * 32 + nt * 8 + 2 * q;
#pragma unroll
                for (int hr = 0; hr < 2; hr++) {
                    int rl = mt * 16 + r + hr * 8;
                    st[rl * 129 + coll]     = acc[mt][nt][hr * 2 + 0];
                    st[rl * 129 + coll + 1] = acc[mt][nt][hr * 2 + 1];
                }
            }
        }
        __syncthreads();
        int n = rbase >> 6;
        int l = tid & 63;
        int c0 = tid >> 6;
#pragma unroll
        for (int it = 0; it < 64; it++) {
            int col = c0 + it * 2;
            outp[((size_t)n * G3 + j0 + col) * 64 + l] = st[l * 129 + col];
        }
    }
}

// ---------------------------------------------------------------------------
// P2: attention scores. 256 blocks: n = b&31, lg = b>>5 (8 l each)
// ---------------------------------------------------------------------------
__device__ __forceinline__ void score_body(int b, const float* __restrict__ v_att,
                                           float* sm) {
    float* sdec = sm;
    float* sv   = sm + 1024;
    int n = b & 31, lg = b >> 5;
    int tid = threadIdx.x;
    for (int i = tid; i < 1024; i += 128) {
        float s = 0.f;
#pragma unroll
        for (int sp = 0; sp < 8; sp++)
            s += g_dp_part[((size_t)sp * NB + n) * 1024 + i];
        sdec[i] = s;
        sv[i] = v_att[i];
    }
    __syncthreads();
    int w = tid >> 5, lane = tid & 31;
#pragma unroll
    for (int li = 0; li < 2; li++) {
        int l = lg * 8 + w * 2 + li;
        const float* ep = g_enc_proj + ((size_t)n * 64 + l) * 1024;
        float s = 0.f;
        for (int a = lane; a < 1024; a += 32)
            s += tanh_fast(ep[a] + sdec[a]) * sv[a];
#pragma unroll
        for (int o = 16; o; o >>= 1) s += __shfl_xor_sync(0xffffffffu, s, o);
        if (lane == 0) g_score[n * 64 + l] = s;
    }
}

// ---------------------------------------------------------------------------
// P3: softmax + gi0 (att@encWih0T + precomp0) + combine0 -> h0
// ---------------------------------------------------------------------------
__device__ __forceinline__ void gi0comb_body(int b, int t,
                                             const float* __restrict__ b_ih,
                                             const float* __restrict__ b_hh,
                                             float* __restrict__ out,
                                             float* sm) {
    float* satt = sm;
    int n = b & 31, jg = b >> 5;
    int tid = threadIdx.x;
    if (tid < 32) {
        float a0 = g_score[n * 64 + tid], a1 = g_score[n * 64 + tid + 32];
        float m = fmaxf(a0, a1);
#pragma unroll
        for (int o = 16; o; o >>= 1) m = fmaxf(m, __shfl_xor_sync(0xffffffffu, m, o));
        float e0 = __expf(a0 - m), e1 = __expf(a1 - m);
        float sum = e0 + e1;
#pragma unroll
        for (int o = 16; o; o >>= 1) sum += __shfl_xor_sync(0xffffffffu, sum, o);
        float inv = 1.f / sum;
        satt[tid]      = e0 * inv;
        satt[tid + 32] = e1 * inv;
        if (jg == 0) {
            out[ATT_BASE + ((size_t)n * 64 + tid)      * TSTEP + t] = e0 * inv;
            out[ATT_BASE + ((size_t)n * 64 + tid + 32) * TSTEP + t] = e1 * inv;
        }
    }
    __syncthreads();

    int j = jg * 128 + tid;
    const float* base = g_encWih0T + (size_t)n * G3 * 64;
    const float4* pr = (const float4*)(base + (size_t)j * 64);
    const float4* pz = (const float4*)(base + (size_t)(1024 + j) * 64);
    const float4* pn = (const float4*)(base + (size_t)(2048 + j) * 64);
    float dr = 0.f, dz = 0.f, dn = 0.f;
#pragma unroll
    for (int lq = 0; lq < 16; lq++) {
        float a0 = satt[lq * 4 + 0], a1 = satt[lq * 4 + 1];
        float a2 = satt[lq * 4 + 2], a3 = satt[lq * 4 + 3];
        float4 vr = pr[lq], vz = pz[lq], vn = pn[lq];
        dr += a0 * vr.x + a1 * vr.y + a2 * vr.z + a3 * vr.w;
        dz += a0 * vz.x + a1 * vz.y + a2 * vz.z + a3 * vz.w;
        dn += a0 * vn.x + a1 * vn.y + a2 * vn.z + a3 * vn.w;
    }
    const float* pc = g_precomp0 + ((size_t)t * NB + n) * G3;
    float gir = pc[j]        + dr + b_ih[j];
    float giz = pc[1024 + j] + dz + b_ih[1024 + j];
    float gin = pc[2048 + j] + dn + b_ih[2048 + j];
    float ghr = b_hh[j], ghz = b_hh[1024 + j], ghn = b_hh[2048 + j];
#pragma unroll
    for (int s = 0; s < 8; s++) {
        const float* gp = g_gh0_part + ((size_t)s * NB + n) * G3;
        ghr += gp[j]; ghz += gp[1024 + j]; ghn += gp[2048 + j];
    }
    float rr = 1.f / (1.f + expf(-(gir + ghr)));
    float zz = 1.f / (1.f + expf(-(giz + ghz)));
    float nn = tanhf(gin + rr * ghn);
    float* h0 = g_h + n * HID;
    h0[j] = (1.f - zz) * nn + zz * h0[j];
}

// ---------------------------------------------------------------------------
// comb1: 8 gi + 8 gh parts + biases -> h1 + dec_hids out
// ---------------------------------------------------------------------------
__device__ __forceinline__ void add4(float* a, float4 v) {
    a[0] += v.x; a[1] += v.y; a[2] += v.z; a[3] += v.w;
}

__device__ __forceinline__ void combine1_body(int t, int n,
                                              const float* __restrict__ b_ih_l,
                                              const float* __restrict__ b_hh_l,
                                              float* __restrict__ out_hid) {
    int tid = threadIdx.x;
    float* h = g_h + NB * HID + n * HID;
#pragma unroll
    for (int half = 0; half < 2; half++) {
        int j = tid * 4 + half * 512;
        float gi[3][4] = {}, gh[3][4] = {};
#pragma unroll
        for (int g = 0; g < 3; g++) {
#pragma unroll
            for (int s = 0; s < 8; s++) {
                add4(gi[g], *(const float4*)(g_gi_part  + ((size_t)s * NB + n) * G3 + g * 1024 + j));
                add4(gh[g], *(const float4*)(g_gh1_part + ((size_t)s * NB + n) * G3 + g * 1024 + j));
            }
            add4(gi[g], *(const float4*)(b_ih_l + g * 1024 + j));
            add4(gh[g], *(const float4*)(b_hh_l + g * 1024 + j));
        }
        float4 ho = *(const float4*)(h + j);
        float ho_[4] = {ho.x, ho.y, ho.z, ho.w};
        float hn_[4];
#pragma unroll
        for (int c = 0; c < 4; c++) {
            float r  = 1.f / (1.f + expf(-(gi[0][c] + gh[0][c])));
            float z  = 1.f / (1.f + expf(-(gi[1][c] + gh[1][c])));
            float nn = tanhf(gi[2][c] + r * gh[2][c]);
            hn_[c] = (1.f - z) * nn + z * ho_[c];
        }
        float4 hv = {hn_[0], hn_[1], hn_[2], hn_[3]};
        *(float4*)(h + j) = hv;
        *(float4*)(out_hid + ((size_t)n * TSTEP + t) * 1024 + j) = hv;
    }
}

// ---------------------------------------------------------------------------
// Persistent decode kernel: 5 grid barriers per step
// ---------------------------------------------------------------------------
__global__ void __launch_bounds__(128) decode_kernel(
        const float* __restrict__ dec_init,
        const float* __restrict__ W_att_dec,
        const float* __restrict__ W_hh,
        const float* __restrict__ W_ih,
        const float* __restrict__ b_ih,
        const float* __restrict__ b_hh,
        const float* __restrict__ v_att,
        float* __restrict__ out) {
    __shared__ float sm[23040];   // 92160 B: 4-buffer GEMM pipeline
    int b = blockIdx.x;
    int tid = threadIdx.x;
    unsigned ph = 0;

    if (b < 32) {
        for (int i = b * 128 + tid; i < 2 * NB * HID; i += 32 * 128)
            g_h[i] = dec_init[i];
    } else if (b >= 64) {
        int x = b - 64;
        int tile = x >> 3, split = x & 7;
        gemm_tc4(dec_init, W_hh, G3, tile * 128, split * 128,
                 g_gh0_part + (size_t)split * NB * G3, sm);
    }
    gridbar(++ph);

    for (int t = 0; t < TSTEP; t++) {
        if (b < 64) {
            int tile = b >> 3, split = b & 7;
            gemm_tc4(g_h + NB * HID, W_att_dec, 1024, tile * 128, split * 128,
                     g_dp_part + (size_t)split * NB * 1024, sm);
        } else {
            int x = b - 64;
            int tile = x >> 3, split = x & 7;
            gemm_tc4(g_h + NB * HID, W_hh + (size_t)G3 * 1024, G3, tile * 128,
                     split * 128, g_gh1_part + (size_t)split * NB * G3, sm);
        }
        gridbar(++ph);

        score_body(b, v_att, sm);
        gridbar(++ph);

        gi0comb_body(b, t, b_ih, b_hh, out, sm);
        gridbar(++ph);

        if (b < 192) {
            int tile = b >> 3, split = b & 7;
            gemm_tc4(g_h, W_ih + (size_t)G3 * 1024, G3, tile * 128, split * 128,
                     g_gi_part + (size_t)split * NB * G3, sm);
        }
        gridbar(++ph);

        if (b < 32) {
            combine1_body(t, b, b_ih + G3, b_hh + G3, out);
        } else if (b >= 64) {
            int x = b - 64;
            int tile = x >> 3, split = x & 7;
            gemm_tc4(g_h, W_hh, G3, tile * 128, split * 128,
                     g_gh0_part + (size_t)split * NB * G3, sm);
        }
        gridbar(++ph);
    }

    for (int i = b * 128 + tid; i < 2 * NB * HID; i += NBLK * 128)
        out[DECPREV_BASE + i] = g_h[i];
}

// ---------------------------------------------------------------------------
// Prologue 0: embedding gather + bias precompute + barrier reset
// ---------------------------------------------------------------------------
__global__ void prol_setup(const int* __restrict__ input_ids,
                           const float* __restrict__ emb_table,
                           const float* __restrict__ b_in,
                           const float* __restrict__ b_ctx) {
    int b = blockIdx.x, tid = threadIdx.x;
    if (b < TSTEP * NB) {
        int t = b >> 5, n = b & 31;
        int id = input_ids[n * 64 + t];
        float4 v = *(const float4*)(emb_table + (size_t)id * 1024 + tid * 4);
        *(float4*)(g_emb_src + (size_t)b * 1024 + tid * 4) = v;
    } else {
        float4 bi = *(const float4*)(b_in + tid * 4);
        float4 bc = *(const float4*)(b_ctx + tid * 4);
        *(float4*)(g_bias + tid * 4) =
            make_float4(bi.x + bc.x, bi.y + bc.y, bi.z + bc.z, bi.w + bc.w);
        if (tid == 0) g_bar_cnt = 0;
    }
}

// ---------------------------------------------------------------------------
// Prologue 1 (fp32): enc_proj only. 512 x 256.
// ---------------------------------------------------------------------------
__global__ void prol_fp32(const float* __restrict__ enc_hids,
                          const float* __restrict__ W_att_enc) {
    __shared__ float As[2][32 * 68];
    __shared__ float Ws[2][32 * 68];
    int b = blockIdx.x;
    int rt = b >> 4, ct = b & 15;
    int r0 = rt * 64, c0 = ct * 64;
    int tid = threadIdx.x;
    int lp = tid & 7, lr = tid >> 3;
    int tx = tid & 15, ty = tid >> 4;
    const float* W = W_att_enc;

    float4 a[2], wv[2];
#define PROL_FETCH(k0)                                                          \
    {                                                                           \
        _Pragma("unroll")                                                       \
        for (int h = 0; h < 2; h++) {                                           \
            int gr = r0 + lr + h * 32;                                          \
            a[h] = *(const float4*)(enc_hids + (size_t)gr * 1024 + (k0) + lp * 4); \
            wv[h] = *(const float4*)(W + (size_t)(c0 + lr + h * 32) * 1024 + (k0) + lp * 4); \
        }                                                                       \
    }
#define PROL_STORE(buf)                                                         \
    {                                                                           \
        _Pragma("unroll")                                                       \
        for (int h = 0; h < 2; h++) {                                           \
            int rr = lr + h * 32;                                               \
            As[buf][(lp * 4 + 0) * 68 + rr] = a[h].x;                           \
            As[buf][(lp * 4 + 1) * 68 + rr] = a[h].y;                           \
            As[buf][(lp * 4 + 2) * 68 + rr] = a[h].z;                           \
            As[buf][(lp * 4 + 3) * 68 + rr] = a[h].w;                           \
            Ws[buf][(lp * 4 + 0) * 68 + rr] = wv[h].x;                          \
            Ws[buf][(lp * 4 + 1) * 68 + rr] = wv[h].y;                          \
            Ws[buf][(lp * 4 + 2) * 68 + rr] = wv[h].z;                          \
            Ws[buf][(lp * 4 + 3) * 68 + rr] = wv[h].w;                          \
        }                                                                       \
    }

    float acc[4][4];
#pragma unroll
    for (int i = 0; i < 4; i++)
#pragma unroll
        for (int j = 0; j < 4; j++) acc[i][j] = 0.f;

    PROL_FETCH(0);
    PROL_STORE(0);
    __syncthreads();
    for (int c = 0; c < 32; c++) {
        const float* as = As[c & 1];
        const float* ws = Ws[c & 1];
        if (c + 1 < 32) PROL_FETCH((c + 1) * 32);
#pragma unroll
        for (int kk = 0; kk < 32; kk++) {
            float4 a4 = *(const float4*)&as[kk * 68 + ty * 4];
            float4 b4 = *(const float4*)&ws[kk * 68 + tx * 4];
            float avv[4] = {a4.x, a4.y, a4.z, a4.w};
            float bvv[4] = {b4.x, b4.y, b4.z, b4.w};
#pragma unroll
            for (int i = 0; i < 4; i++)
#pragma unroll
                for (int j = 0; j < 4; j++) acc[i][j] += avv[i] * bvv[j];
        }
        if (c + 1 < 32) {
            PROL_STORE((c + 1) & 1);
            __syncthreads();
        }
    }
#pragma unroll
    for (int i = 0; i < 4; i++) {
        int rr = r0 + ty * 4 + i;
#pragma unroll
        for (int j = 0; j < 4; j++) {
            int cc = c0 + tx * 4 + j;
            g_enc_proj[(size_t)rr * 1024 + cc] = acc[i][j];
        }
    }
#undef PROL_FETCH
#undef PROL_STORE
}

// ---------------------------------------------------------------------------
// Prologue 2 (tf32, M=64): encW (256 blocks) + emb_merged (+bias, 256 blocks)
// ---------------------------------------------------------------------------
__global__ void __launch_bounds__(128) prol_tc1(const float* __restrict__ enc_hids,
                                                const float* __restrict__ W_ctx,
                                                const float* __restrict__ W_in) {
    __shared__ float sm[13824];
    int b = blockIdx.x;
    if (b < 256) {
        int rt = b >> 3, ct = b & 7;
        gemm_tc_long64(enc_hids + (size_t)rt * 64 * 1024, W_ctx, 1024, ct * 128,
                       0, 0, nullptr, g_encW + (size_t)rt * 64 * 1024, sm);
    } else {
        int x = b - 256;
        int rt = x >> 3, ct = x & 7;
        gemm_tc_long64(g_emb_src + (size_t)rt * 64 * 1024, W_in, 1024, ct * 128,
                       0, 0, g_bias, g_emb_merged + (size_t)rt * 64 * 1024, sm);
    }
}

// ---------------------------------------------------------------------------
// Prologue 3 (tf32, M=64): encWih0T (transposed) + precomp0. 1536 x 128.
// ---------------------------------------------------------------------------
__global__ void __launch_bounds__(128) prol_tc2(const float* __restrict__ W_ih) {
    __shared__ float sm[13824];
    int b = blockIdx.x;
    if (b < 768) {
        int rt = b / 24, ct = b % 24;
        gemm_tc_long64(g_encW + (size_t)rt * 64 * 1024, W_ih, G3,
                       ct * 128, rt * 64, 1, nullptr, g_encWih0T, sm);
    } else {
        int x = b - 768;
        int rt = x / 24, ct = x % 24;
        gemm_tc_long64(g_emb_merged + (size_t)rt * 64 * 1024, W_ih, G3,
                       ct * 128, 0, 0, nullptr,
                       g_precomp0 + (size_t)rt * 64 * G3, sm);
    }
}

// ---------------------------------------------------------------------------
extern "C" void kernel_launch(void* const* d_in, const int* in_sizes, int n_in,
                              void* d_out, int out_size) {
    const int*   input_ids = (const int*)  d_in[0];
    const float* dec_init  = (const float*)d_in[1];
    const float* enc_hids  = (const float*)d_in[2];
    const float* emb_table = (const float*)d_in[3];
    const float* W_in      = (const float*)d_in[4];
    const float* b_in      = (const float*)d_in[5];
    const float* W_ctx     = (const float*)d_in[6];
    const float* b_ctx     = (const float*)d_in[7];
    const float* W_att_dec = (const float*)d_in[8];
    const float* W_att_enc = (const float*)d_in[9];
    const float* v_att     = (const float*)d_in[10];
    const float* W_ih      = (const float*)d_in[11];
    const float* W_hh      = (const float*)d_in[12];
    const float* b_ih      = (const float*)d_in[13];
    const float* b_hh      = (const float*)d_in[14];
    float* out = (float*)d_out;

    prol_setup<<<TSTEP * NB + 1, 256>>>(input_ids, emb_table, b_in, b_ctx);
    prol_fp32<<<512, 256>>>(enc_hids, W_att_enc);
    prol_tc1<<<512, 128>>>(enc_hids, W_ctx, W_in);
    prol_tc2<<<1536, 128>>>(W_ih);
    decode_kernel<<<NBLK, 128>>>(dec_init, W_att_dec, W_hh, W_ih,
                                 b_ih, b_hh, v_att, out);
}